// round 3
// baseline (speedup 1.0000x reference)
#include <cuda_runtime.h>

// Problem dims (fixed by the dataset): pred [8,4,256,256] f32, target [8,256,256] i32,
// boundary_weight [8,1,256,256] f32, output: scalar f32.
#define BQ 8
#define HQ 256
#define WQ 256
#define HWQ (HQ * WQ)
#define NPIX (BQ * HWQ)
#define BIGD2 (1 << 28)

// Scratch: __device__ globals only (harness-sanctioned). All fully overwritten
// every run -> no init kernel needed, fully deterministic.
__device__ int   g_counts[BQ * 3];     // pixel count of class c (c=1..3) per image
__device__ float g_partial[BQ * HQ];   // one partial sum per block of main kernel

// ---------------------------------------------------------------------------
// Kernel 1: per-image class counts (for degenerate-class detection).
// Grid: 8 blocks (one per image), 256 threads (one per column).
// Reads are fully coalesced (warp spans consecutive j at each row step).
// ---------------------------------------------------------------------------
__global__ void cwbl_counts_kernel(const int* __restrict__ target) {
    const int b = blockIdx.x;
    const int j = threadIdx.x;
    const int* tb = target + b * HWQ;

    int c1 = 0, c2 = 0, c3 = 0;
#pragma unroll 8
    for (int r = 0; r < HQ; ++r) {
        int v = tb[r * WQ + j];
        c1 += (v == 1);
        c2 += (v == 2);
        c3 += (v == 3);
    }
#pragma unroll
    for (int o = 16; o > 0; o >>= 1) {
        c1 += __shfl_down_sync(0xffffffffu, c1, o);
        c2 += __shfl_down_sync(0xffffffffu, c2, o);
        c3 += __shfl_down_sync(0xffffffffu, c3, o);
    }
    __shared__ int s1[8], s2[8], s3[8];
    const int wid = j >> 5, lid = j & 31;
    if (lid == 0) { s1[wid] = c1; s2[wid] = c2; s3[wid] = c3; }
    __syncthreads();
    if (j == 0) {
        int t1 = 0, t2 = 0, t3 = 0;
#pragma unroll
        for (int k = 0; k < 8; ++k) { t1 += s1[k]; t2 += s2[k]; t3 += s3[k]; }
        g_counts[b * 3 + 0] = t1;
        g_counts[b * 3 + 1] = t2;
        g_counts[b * 3 + 2] = t3;
    }
}

// ---------------------------------------------------------------------------
// Kernel 2: fused softmax + exact nearest-opposite-class distance (expanding
// Chebyshev-ring search) + weighted-error accumulation.
// Grid: 2048 blocks (one per (b, row i)), 256 threads (one per column j).
//
// Exactness: for output pixel p and class c,
//   dist_c(p) = edt(m_c)(p) + edt(~m_c)(p)
//             = sqrt(d2 to nearest pixel with target==c)   if target(p) != c
//             = sqrt(d2 to nearest pixel with target!=c)   if target(p) == c
// Ring r only contains pixels with d2 >= r*r, so once r*r >= every needed
// best-d2, the search is provably complete. Degenerate classes contribute 0
// and are excluded from the termination requirement.
// ---------------------------------------------------------------------------
__global__ void cwbl_main_kernel(const float* __restrict__ pred,
                                 const int*   __restrict__ target,
                                 const float* __restrict__ wgt) {
    const int bi = blockIdx.x;      // b*HQ + i
    const int b  = bi >> 8;
    const int i  = bi & (HQ - 1);
    const int j  = threadIdx.x;

    const int* tb  = target + b * HWQ;
    const int base = i * WQ + j;

    const int   t = tb[base];
    const float w = wgt[b * HWQ + base];

    // --- softmax over 4 channels ---
    const float* pb = pred + (size_t)b * 4 * HWQ;
    const float x0 = pb[base];
    const float x1 = pb[HWQ + base];
    const float x2 = pb[2 * HWQ + base];
    const float x3 = pb[3 * HWQ + base];
    const float mx = fmaxf(fmaxf(x0, x1), fmaxf(x2, x3));
    const float e0 = __expf(x0 - mx);
    const float e1 = __expf(x1 - mx);
    const float e2 = __expf(x2 - mx);
    const float e3 = __expf(x3 - mx);
    const float rd = 1.0f / (e0 + e1 + e2 + e3);

    // --- degenerate-class flags ---
    const int cnt1 = g_counts[b * 3 + 0];
    const int cnt2 = g_counts[b * 3 + 1];
    const int cnt3 = g_counts[b * 3 + 2];
    const bool deg1 = (cnt1 == 0) || (cnt1 == HWQ);
    const bool deg2 = (cnt2 == 0) || (cnt2 == HWQ);
    const bool deg3 = (cnt3 == 0) || (cnt3 == HWQ);

    // --- expanding ring search for nearest pixel of each class value ---
    int bd0 = BIGD2, bd1 = BIGD2, bd2 = BIGD2, bd3 = BIGD2;
    if      (t == 0) bd0 = 0;
    else if (t == 1) bd1 = 0;
    else if (t == 2) bd2 = 0;
    else             bd3 = 0;

#pragma unroll 1
    for (int r = 1; r < 256; ++r) {
        // nearest pixel of a class != t (needed when t is the class itself)
        int mo = BIGD2;
        if (t != 0) mo = min(mo, bd0);
        if (t != 1) mo = min(mo, bd1);
        if (t != 2) mo = min(mo, bd2);
        if (t != 3) mo = min(mo, bd3);

        int M = 0;
        if (!deg1) M = max(M, (t == 1) ? mo : bd1);
        if (!deg2) M = max(M, (t == 2) ? mo : bd2);
        if (!deg3) M = max(M, (t == 3) ? mo : bd3);
        if (r * r >= M) break;

        const int r2   = r * r;
        const int itop = i - r;
        const int ibot = i + r;
        const bool okT = (itop >= 0);
        const bool okB = (ibot < HQ);
        const int* rowT = tb + itop * WQ;
        const int* rowB = tb + ibot * WQ;

        // top & bottom rows of the ring
#pragma unroll 1
        for (int dj = -r; dj <= r; ++dj) {
            const int jj = j + dj;
            if ((unsigned)jj >= (unsigned)WQ) continue;
            const int d2 = r2 + dj * dj;
            if (okT) {
                const int v = __ldg(&rowT[jj]);
                bd0 = min(bd0, (v == 0) ? d2 : BIGD2);
                bd1 = min(bd1, (v == 1) ? d2 : BIGD2);
                bd2 = min(bd2, (v == 2) ? d2 : BIGD2);
                bd3 = min(bd3, (v == 3) ? d2 : BIGD2);
            }
            if (okB) {
                const int v = __ldg(&rowB[jj]);
                bd0 = min(bd0, (v == 0) ? d2 : BIGD2);
                bd1 = min(bd1, (v == 1) ? d2 : BIGD2);
                bd2 = min(bd2, (v == 2) ? d2 : BIGD2);
                bd3 = min(bd3, (v == 3) ? d2 : BIGD2);
            }
        }

        // left & right columns of the ring (excluding corners)
        const int jl = j - r;
        const int jr = j + r;
        const bool okL = (jl >= 0);
        const bool okR = (jr < WQ);
#pragma unroll 1
        for (int di = -r + 1; di <= r - 1; ++di) {
            const int ii = i + di;
            if ((unsigned)ii >= (unsigned)HQ) continue;
            const int d2  = di * di + r2;
            const int* row = tb + ii * WQ;
            if (okL) {
                const int v = __ldg(&row[jl]);
                bd0 = min(bd0, (v == 0) ? d2 : BIGD2);
                bd1 = min(bd1, (v == 1) ? d2 : BIGD2);
                bd2 = min(bd2, (v == 2) ? d2 : BIGD2);
                bd3 = min(bd3, (v == 3) ? d2 : BIGD2);
            }
            if (okR) {
                const int v = __ldg(&row[jr]);
                bd0 = min(bd0, (v == 0) ? d2 : BIGD2);
                bd1 = min(bd1, (v == 1) ? d2 : BIGD2);
                bd2 = min(bd2, (v == 2) ? d2 : BIGD2);
                bd3 = min(bd3, (v == 3) ? d2 : BIGD2);
            }
        }
    }

    // final min-over-others (for pixels whose own class is being scored)
    int mo = BIGD2;
    if (t != 0) mo = min(mo, bd0);
    if (t != 1) mo = min(mo, bd1);
    if (t != 2) mo = min(mo, bd2);
    if (t != 3) mo = min(mo, bd3);

    // --- loss contributions for classes 1..3 ---
    float acc = 0.0f;
    {
        const float dist = deg1 ? 0.0f : sqrtf((float)((t == 1) ? mo : bd1));
        const float tc = (t == 1) ? 1.0f : 0.0f;
        acc += fabsf(e1 * rd - tc) * dist;
    }
    {
        const float dist = deg2 ? 0.0f : sqrtf((float)((t == 2) ? mo : bd2));
        const float tc = (t == 2) ? 1.0f : 0.0f;
        acc += fabsf(e2 * rd - tc) * dist;
    }
    {
        const float dist = deg3 ? 0.0f : sqrtf((float)((t == 3) ? mo : bd3));
        const float tc = (t == 3) ? 1.0f : 0.0f;
        acc += fabsf(e3 * rd - tc) * dist;
    }
    acc *= w;

    // --- block reduction -> deterministic per-block partial (no atomics) ---
#pragma unroll
    for (int o = 16; o > 0; o >>= 1)
        acc += __shfl_down_sync(0xffffffffu, acc, o);
    __shared__ float sa[8];
    const int wid = j >> 5, lid = j & 31;
    if (lid == 0) sa[wid] = acc;
    __syncthreads();
    if (j == 0) {
        float s = 0.0f;
#pragma unroll
        for (int k = 0; k < 8; ++k) s += sa[k];
        g_partial[blockIdx.x] = s;
    }
}

// ---------------------------------------------------------------------------
// Kernel 3: deterministic final reduction of 2048 partials.
// ---------------------------------------------------------------------------
__global__ void cwbl_finalize_kernel(float* __restrict__ out) {
    __shared__ double sd[256];
    double s = 0.0;
    for (int k = threadIdx.x; k < BQ * HQ; k += 256)
        s += (double)g_partial[k];
    sd[threadIdx.x] = s;
    __syncthreads();
#pragma unroll
    for (int st = 128; st > 0; st >>= 1) {
        if (threadIdx.x < st) sd[threadIdx.x] += sd[threadIdx.x + st];
        __syncthreads();
    }
    if (threadIdx.x == 0)
        out[0] = (float)(sd[0] / (3.0 * (double)NPIX));
}

// ---------------------------------------------------------------------------
extern "C" void kernel_launch(void* const* d_in, const int* in_sizes, int n_in,
                              void* d_out, int out_size) {
    const float* pred   = (const float*)d_in[0];
    const int*   target = (const int*)d_in[1];
    const float* wgt    = (const float*)d_in[2];
    float* out = (float*)d_out;
    (void)in_sizes; (void)n_in; (void)out_size;

    cwbl_counts_kernel<<<BQ, 256>>>(target);
    cwbl_main_kernel<<<BQ * HQ, 256>>>(pred, target, wgt);
    cwbl_finalize_kernel<<<1, 256>>>(out);
}